// round 15
// baseline (speedup 1.0000x reference)
#include <cuda_runtime.h>
#include <cuda_fp16.h>
#include <cstdint>

#define NPTS 131072
#define BSEG 16
#define EPSF 1e-5f

// ================= device scratch (allocation-free) =================
__device__ __half d_a2[(size_t)NPTS * 256];
__device__ __half d_a3[(size_t)NPTS * 512];
__device__ __half d_w2[256 * 128];
__device__ __half d_w3[512 * 256];
__device__ __half d_w4[1024 * 512];
__device__ float d_W1c[128 * 4];            // [c][w0,w1,w2,bias]
__device__ float d_b2f[256], d_b3f[512], d_b4f[1024];
__device__ float d_u[512 * BSEG];           // per-segment bias for layer3
__device__ unsigned d_gkey[BSEG * 256];
__device__ unsigned d_vkey[BSEG * 1024];
__device__ int d_seg[NPTS];

// ================= helpers =================
__device__ __forceinline__ unsigned f2key(float f) {
    unsigned u = __float_as_uint(f);
    return (u & 0x80000000u) ? ~u : (u | 0x80000000u);
}
__device__ __forceinline__ float key2f(unsigned k) {
    return (k & 0x80000000u) ? __uint_as_float(k & 0x7FFFFFFFu)
                             : __uint_as_float(~k);
}
__device__ __forceinline__ uint32_t smem_to_u32(const void* p) {
    uint32_t a;
    asm("{ .reg .u64 t; cvta.to.shared.u64 t, %1; cvt.u32.u64 %0, t; }" : "=r"(a) : "l"(p));
    return a;
}
#define SW128(o) ((o) ^ (((o) >> 3) & 0x70))

// ---- baseline-PTX tensor ops ----
__device__ __forceinline__ void ldsm4(uint32_t (&r)[4], uint32_t addr) {
    asm volatile("ldmatrix.sync.aligned.m8n8.x4.shared.b16 {%0,%1,%2,%3}, [%4];"
                 : "=r"(r[0]), "=r"(r[1]), "=r"(r[2]), "=r"(r[3]) : "r"(addr));
}
__device__ __forceinline__ void mma16816(float (&d)[4], const uint32_t (&a)[4],
                                         uint32_t b0, uint32_t b1) {
    asm volatile("mma.sync.aligned.m16n8k16.row.col.f32.f16.f16.f32 "
                 "{%0,%1,%2,%3}, {%4,%5,%6,%7}, {%8,%9}, {%0,%1,%2,%3};"
                 : "+f"(d[0]), "+f"(d[1]), "+f"(d[2]), "+f"(d[3])
                 : "r"(a[0]), "r"(a[1]), "r"(a[2]), "r"(a[3]), "r"(b0), "r"(b1));
}
__device__ __forceinline__ void cpasync16(uint32_t saddr, const void* g) {
    asm volatile("cp.async.cg.shared.global [%0], [%1], 16;" :: "r"(saddr), "l"(g));
}
#define CP_COMMIT() asm volatile("cp.async.commit_group;" ::: "memory")
#define CP_WAIT(N)  asm volatile("cp.async.wait_group %0;" :: "n"(N) : "memory")

// ================= setup =================
// Kdst is a power of two -> shift/mask indexing (no integer divide in the hot fold loops)
template<int SH>
__device__ __forceinline__ void fold_single(int t0, int stride,
        const float* __restrict__ W, const float* __restrict__ g, const float* __restrict__ v,
        __half* wd, int C, int Ksrc, int Koff) {
    constexpr int Kdst = 1 << SH;
    for (int idx = t0; idx < C * Kdst; idx += stride) {
        int c = idx >> SH, k = idx & (Kdst - 1);
        float s = g[c] * rsqrtf(v[c] + EPSF);
        wd[idx] = __float2half_rn(s * W[(size_t)c * Ksrc + Koff + k]);
    }
}
__device__ __forceinline__ void fold_bias(int t0, int stride,
        const float* b, const float* g, const float* be, const float* m, const float* v,
        float* bf, int C) {
    for (int i = t0; i < C; i += stride) {
        float s = g[i] * rsqrtf(v[i] + EPSF);
        bf[i] = s * b[i] + be[i] - s * m[i];
    }
}

__global__ void setup_kernel(const int* __restrict__ npts,
    const float* W1, const float* b1, const float* g1, const float* be1, const float* m1, const float* v1,
    const float* W2, const float* b2, const float* g2, const float* be2, const float* m2, const float* v2,
    const float* W3, const float* b3, const float* g3, const float* be3, const float* m3, const float* v3,
    const float* W4, const float* b4, const float* g4, const float* be4, const float* m4, const float* v4) {
    const int stride = gridDim.x * blockDim.x;
    const int t0 = blockIdx.x * blockDim.x + threadIdx.x;

    for (int c = t0; c < 128; c += stride) {
        float s = g1[c] * rsqrtf(v1[c] + EPSF);
        d_W1c[c * 4 + 0] = s * W1[c * 3 + 0];
        d_W1c[c * 4 + 1] = s * W1[c * 3 + 1];
        d_W1c[c * 4 + 2] = s * W1[c * 3 + 2];
        d_W1c[c * 4 + 3] = s * b1[c] + be1[c] - s * m1[c];
    }
    fold_single<7>(t0, stride, W2, g2, v2, d_w2, 256,  128, 0);
    fold_single<8>(t0, stride, W3, g3, v3, d_w3, 512,  512, 256);
    fold_single<9>(t0, stride, W4, g4, v4, d_w4, 1024, 512, 0);
    fold_bias(t0, stride, b2, g2, be2, m2, v2, d_b2f, 256);
    fold_bias(t0, stride, b3, g3, be3, m3, v3, d_b3f, 512);
    fold_bias(t0, stride, b4, g4, be4, m4, v4, d_b4f, 1024);

    int cum[BSEG];
    {
        int a = 0;
        #pragma unroll
        for (int t = 0; t < BSEG; t++) { a += __ldg(&npts[t]); cum[t] = a; }
    }
    for (int j = t0; j < NPTS; j += stride) {
        int s = 0;
        #pragma unroll
        for (int t = 0; t < BSEG - 1; t++) s += (j >= cum[t]);
        d_seg[j] = s;
    }
    for (int i = t0; i < BSEG * 1024; i += stride) d_vkey[i] = 0u;
    for (int i = t0; i < BSEG * 256;  i += stride) d_gkey[i] = 0u;
}

__global__ void fin_v_kernel(float* __restrict__ out) {
    int i = blockIdx.x * blockDim.x + threadIdx.x;
    if (i < BSEG * 1024) out[i] = key2f(d_vkey[i]);
}
__global__ void k_u_kernel(const float* __restrict__ W3,
                           const float* __restrict__ g3,
                           const float* __restrict__ v3) {
    int w = (blockIdx.x * blockDim.x + threadIdx.x) >> 5;
    int lane = threadIdx.x & 31;
    if (w >= 512 * BSEG) return;
    int m = w >> 4, s = w & 15;
    float acc = 0.0f;
    for (int r = lane; r < 256; r += 32)
        acc += W3[(size_t)m * 512 + r] * key2f(d_gkey[s * 256 + r]);
    #pragma unroll
    for (int o = 16; o; o >>= 1) acc += __shfl_xor_sync(0xffffffffu, acc, o);
    if (lane == 0) d_u[m * BSEG + s] = g3[m] * rsqrtf(v3[m] + EPSF) * acc;
}

// ================= mma.sync GEMM (R12 structure, byte-exact compute) =================
// CTA: 128 pts x 128 chans; 8 warps 4(m) x 2(n); per-warp 32x64.
// K chunks of 64; 3 stages; swizzled 128B rows. 98 KB smem/CTA -> 2 CTAs/SM.
#define ROWB    128
#define ATILE   (128 * ROWB)          // 16384
#define BTILE   (128 * ROWB)          // 16384
#define STAGEB  (ATILE + BTILE)       // 32768
#define NSTAGE  3
#define RED_OFF (NSTAGE * STAGEB)     // float red[8][64] = 2048 B
#define MM_SMEM (RED_OFF + 2048)      // 100352 B

template<int CFG>
__global__ void __launch_bounds__(256, 2) mm_kernel(const float* __restrict__ xg) {
    constexpr int K    = (CFG == 0) ? 128 : (CFG == 1) ? 256 : 512;
    constexpr int MOUT = (CFG == 0) ? 256 : (CFG == 1) ? 512 : 1024;
    constexpr int KC   = K / 64;
    constexpr bool SEGMAX = (CFG != 1);
    constexpr bool STORE  = (CFG != 2);
    constexpr bool FUSE1  = (CFG == 0);

    const __half* __restrict__ Ain = (CFG == 1) ? d_a2 : d_a3;   // unused for CFG0
    const __half* __restrict__ Bw  = (CFG == 0) ? d_w2 : (CFG == 1) ? d_w3 : d_w4;
    const float* __restrict__ bias = (CFG == 0) ? d_b2f : (CFG == 1) ? d_b3f : d_b4f;
    __half* Oa = (CFG == 0) ? d_a2 : d_a3;
    unsigned* key = (CFG == 0) ? d_gkey : d_vkey;

    extern __shared__ char smem[];
    const uint32_t sb = smem_to_u32(smem);
    const int tid = threadIdx.x, wid = tid >> 5, lane = tid & 31;
    const int wm = wid & 3, wn = wid >> 2;
    const int n0 = blockIdx.x * 128;
    const int pt0 = blockIdx.y * 128;

    float acc[2][8][4];
    #pragma unroll
    for (int mi = 0; mi < 2; mi++)
        #pragma unroll
        for (int nt = 0; nt < 8; nt++)
            #pragma unroll
            for (int q = 0; q < 4; q++) acc[mi][nt][q] = 0.0f;

    auto load_B = [&](int kc, int buf) {
        const int k0 = kc * 64;
        const uint32_t base = sb + (uint32_t)buf * STAGEB;
        #pragma unroll
        for (int i = 0; i < 4; i++) {
            int idx = i * 256 + tid;              // 0..1023
            int row = idx >> 3, c8 = idx & 7;
            cpasync16(base + ATILE + SW128((uint32_t)(row * ROWB + c8 * 16)),
                      Bw + (size_t)(n0 + row) * K + k0 + c8 * 8);
        }
    };
    auto load_chunk = [&](int kc, int buf) {
        const int k0 = kc * 64;
        const uint32_t base = sb + (uint32_t)buf * STAGEB;
        #pragma unroll
        for (int i = 0; i < 4; i++) {
            int idx = i * 256 + tid;
            int row = idx >> 3, c8 = idx & 7;
            cpasync16(base + SW128((uint32_t)(row * ROWB + c8 * 16)),
                      Ain + (size_t)(pt0 + row) * K + k0 + c8 * 8);
        }
        load_B(kc, buf);
        CP_COMMIT();
    };

    // ---- R12 compute (byte-exact): per kk, interleaved ldsm/mma as ptxas schedules ----
    auto compute = [&](int buf) {
        const uint32_t ab = sb + (uint32_t)buf * STAGEB;
        const uint32_t bbB = ab + ATILE;
        #pragma unroll
        for (int kk = 0; kk < 4; kk++) {
            const uint32_t col = (uint32_t)((lane >> 4) * 16 + kk * 32);  // bytes
            uint32_t a_f[2][4];
            #pragma unroll
            for (int mi = 0; mi < 2; mi++) {
                uint32_t row = (uint32_t)(wm * 32 + mi * 16 + (lane & 15));
                ldsm4(a_f[mi], ab + SW128(row * ROWB + col));
            }
            #pragma unroll
            for (int nt4 = 0; nt4 < 4; nt4++) {
                uint32_t row = (uint32_t)(wn * 64 + nt4 * 16 + (lane & 15));
                uint32_t b_f[4];
                ldsm4(b_f, bbB + SW128(row * ROWB + col));
                #pragma unroll
                for (int mi = 0; mi < 2; mi++) {
                    mma16816(acc[mi][nt4 * 2 + 0], a_f[mi], b_f[0], b_f[2]);
                    mma16816(acc[mi][nt4 * 2 + 1], a_f[mi], b_f[1], b_f[3]);
                }
            }
        }
    };

    if (FUSE1) {
        load_B(0, 0); CP_COMMIT();
        load_B(1, 1); CP_COMMIT();
        // layer-1: 2 threads per point; each handles 64 channels -> one K-chunk's A row half
        {
            const int pt = pt0 + (tid >> 1);
            const int half = tid & 1;
            const int row = tid >> 1;
            const float x0 = xg[pt], x1 = xg[NPTS + pt], x2 = xg[2 * NPTS + pt];
            #pragma unroll
            for (int g = 0; g < 8; g++) {
                __half2 h2[4];
                #pragma unroll
                for (int q = 0; q < 4; q++) {
                    #pragma unroll
                    for (int r = 0; r < 2; r++) {
                        const int c = (half * 8 + g) * 8 + q * 2 + r;
                        const float* w = &d_W1c[c * 4];
                        float v = fmaxf(__ldg(&w[3]) + __ldg(&w[0]) * x0
                                      + __ldg(&w[1]) * x1 + __ldg(&w[2]) * x2, 0.0f);
                        if (r == 0) h2[q].x = __float2half_rn(v);
                        else        h2[q].y = __float2half_rn(v);
                    }
                }
                uint32_t off = (uint32_t)half * STAGEB
                             + SW128((uint32_t)(row * ROWB + g * 16));
                *reinterpret_cast<uint4*>(smem + off) = *reinterpret_cast<uint4*>(h2);
            }
        }
    } else {
        load_chunk(0, 0);
        if (KC > 1) load_chunk(1, 1);
    }

    #pragma unroll 1
    for (int kc = 0; kc < KC; kc++) {
        if (kc + 1 < KC) { CP_WAIT(1); } else { CP_WAIT(0); }
        __syncthreads();
        if (!FUSE1 && kc + 2 < KC) load_chunk(kc + 2, (kc + 2) % NSTAGE);
        compute(FUSE1 ? kc : (kc % NSTAGE));
    }

    // ---- epilogue ----
    int ptr_[4], sg[4];
    #pragma unroll
    for (int mi = 0; mi < 2; mi++)
        #pragma unroll
        for (int h = 0; h < 2; h++) {
            int p = pt0 + wm * 32 + mi * 16 + (lane >> 2) + h * 8;
            ptr_[mi * 2 + h] = p;
            sg[mi * 2 + h] = d_seg[p];
        }
    const int cbase = n0 + wn * 64 + (lane & 3) * 2;

    #pragma unroll
    for (int mi = 0; mi < 2; mi++) {
        #pragma unroll
        for (int h = 0; h < 2; h++) {
            const int p = ptr_[mi * 2 + h];
            const int seg = sg[mi * 2 + h];
            #pragma unroll
            for (int nt = 0; nt < 8; nt++) {
                const int c = cbase + nt * 8;
                float v0 = acc[mi][nt][h * 2 + 0] + __ldg(&bias[c]);
                float v1 = acc[mi][nt][h * 2 + 1] + __ldg(&bias[c + 1]);
                if (CFG == 1) {
                    v0 = fmaxf(v0 + d_u[c * BSEG + seg], 0.0f);
                    v1 = fmaxf(v1 + d_u[(c + 1) * BSEG + seg], 0.0f);
                }
                acc[mi][nt][h * 2 + 0] = v0;
                acc[mi][nt][h * 2 + 1] = v1;
                if (STORE) {
                    __half2 hh;
                    hh.x = __float2half_rn(v0);
                    hh.y = __float2half_rn(v1);
                    *reinterpret_cast<uint32_t*>(&Oa[(size_t)p * MOUT + c]) =
                        *reinterpret_cast<uint32_t*>(&hh);
                }
            }
        }
    }

    if (SEGMAX) {
        float* red = reinterpret_cast<float*>(smem + RED_OFF);
        const int s_lo = d_seg[pt0], s_hi = d_seg[pt0 + 127];
        const int np = (s_lo == s_hi) ? 1 : 2;
        for (int pass = 0; pass < np; pass++) {
            const int s = pass ? s_hi : s_lo;
            float cm[8][2];
            #pragma unroll
            for (int nt = 0; nt < 8; nt++) { cm[nt][0] = -3.402823466e38f; cm[nt][1] = -3.402823466e38f; }
            #pragma unroll
            for (int mi = 0; mi < 2; mi++)
                #pragma unroll
                for (int h = 0; h < 2; h++)
                    if (sg[mi * 2 + h] == s) {
                        #pragma unroll
                        for (int nt = 0; nt < 8; nt++) {
                            cm[nt][0] = fmaxf(cm[nt][0], acc[mi][nt][h * 2 + 0]);
                            cm[nt][1] = fmaxf(cm[nt][1], acc[mi][nt][h * 2 + 1]);
                        }
                    }
            #pragma unroll
            for (int o = 4; o < 32; o <<= 1)
                #pragma unroll
                for (int nt = 0; nt < 8; nt++) {
                    cm[nt][0] = fmaxf(cm[nt][0], __shfl_xor_sync(0xffffffffu, cm[nt][0], o));
                    cm[nt][1] = fmaxf(cm[nt][1], __shfl_xor_sync(0xffffffffu, cm[nt][1], o));
                }
            __syncthreads();
            if ((lane >> 2) == 0) {
                #pragma unroll
                for (int nt = 0; nt < 8; nt++) {
                    red[wid * 64 + nt * 8 + (lane & 3) * 2 + 0] = cm[nt][0];
                    red[wid * 64 + nt * 8 + (lane & 3) * 2 + 1] = cm[nt][1];
                }
            }
            __syncthreads();
            if ((wid & 3) == 0) {
                const int wgrp = wid >> 2;
                #pragma unroll
                for (int cc = 0; cc < 2; cc++) {
                    const int col = lane * 2 + cc;
                    float m = red[(wgrp * 4 + 0) * 64 + col];
                    #pragma unroll
                    for (int w = 1; w < 4; w++)
                        m = fmaxf(m, red[(wgrp * 4 + w) * 64 + col]);
                    atomicMax(&key[s * MOUT + n0 + wgrp * 64 + col], f2key(m));
                }
            }
        }
    }
}

// ================= launch =================
extern "C" void kernel_launch(void* const* d_in, const int* in_sizes, int n_in,
                              void* d_out, int out_size) {
    const float* x    = (const float*)d_in[0];
    const int*   npts = (const int*  )d_in[1];
    const float *W1 = (const float*)d_in[2],  *b1 = (const float*)d_in[3],
                *g1 = (const float*)d_in[4],  *be1= (const float*)d_in[5],
                *m1 = (const float*)d_in[6],  *v1 = (const float*)d_in[7];
    const float *W2 = (const float*)d_in[8],  *b2 = (const float*)d_in[9],
                *g2 = (const float*)d_in[10], *be2= (const float*)d_in[11],
                *m2 = (const float*)d_in[12], *v2 = (const float*)d_in[13];
    const float *W3 = (const float*)d_in[14], *b3 = (const float*)d_in[15],
                *g3 = (const float*)d_in[16], *be3= (const float*)d_in[17],
                *m3 = (const float*)d_in[18], *v3 = (const float*)d_in[19];
    const float *W4 = (const float*)d_in[20], *b4 = (const float*)d_in[21],
                *g4 = (const float*)d_in[22], *be4= (const float*)d_in[23],
                *m4 = (const float*)d_in[24], *v4 = (const float*)d_in[25];

    cudaFuncSetAttribute(mm_kernel<0>, cudaFuncAttributeMaxDynamicSharedMemorySize, MM_SMEM);
    cudaFuncSetAttribute(mm_kernel<1>, cudaFuncAttributeMaxDynamicSharedMemorySize, MM_SMEM);
    cudaFuncSetAttribute(mm_kernel<2>, cudaFuncAttributeMaxDynamicSharedMemorySize, MM_SMEM);

    setup_kernel<<<512, 256>>>(npts,
        W1, b1, g1, be1, m1, v1,  W2, b2, g2, be2, m2, v2,
        W3, b3, g3, be3, m3, v3,  W4, b4, g4, be4, m4, v4);

    mm_kernel<0><<<dim3(2, NPTS / 128), 256, MM_SMEM>>>(x);  // #2: f (+g segmax), layer1 fused
    k_u_kernel<<<1024, 256>>>(W3, g3, v3);                   // #3
    mm_kernel<1><<<dim3(4, NPTS / 128), 256, MM_SMEM>>>(x);  // #4: h3
    mm_kernel<2><<<dim3(8, NPTS / 128), 256, MM_SMEM>>>(x);  // #5: v segmax
    fin_v_kernel<<<64, 256>>>((float*)d_out);                // #6
}

// round 16
// speedup vs baseline: 1.0060x; 1.0060x over previous
#include <cuda_runtime.h>
#include <cuda_fp16.h>
#include <cstdint>

#define NPTS 131072
#define BSEG 16
#define EPSF 1e-5f

// ================= device scratch (allocation-free) =================
__device__ __half d_a2[(size_t)NPTS * 256];
__device__ __half d_a3[(size_t)NPTS * 512];
__device__ __half d_w2[256 * 128];
__device__ __half d_w3[512 * 256];
__device__ __half d_w4[1024 * 512];
__device__ float d_W1c[128 * 4];            // [c][w0,w1,w2,bias]
__device__ float d_b2f[256], d_b3f[512], d_b4f[1024];
__device__ float d_u[512 * BSEG];           // per-segment bias for layer3
__device__ unsigned d_gkey[BSEG * 256];
__device__ unsigned d_vkey[BSEG * 1024];
__device__ int d_seg[NPTS];

// ================= helpers =================
__device__ __forceinline__ unsigned f2key(float f) {
    unsigned u = __float_as_uint(f);
    return (u & 0x80000000u) ? ~u : (u | 0x80000000u);
}
__device__ __forceinline__ float key2f(unsigned k) {
    return (k & 0x80000000u) ? __uint_as_float(k & 0x7FFFFFFFu)
                             : __uint_as_float(~k);
}
__device__ __forceinline__ uint32_t smem_to_u32(const void* p) {
    uint32_t a;
    asm("{ .reg .u64 t; cvta.to.shared.u64 t, %1; cvt.u32.u64 %0, t; }" : "=r"(a) : "l"(p));
    return a;
}
#define SW128(o) ((o) ^ (((o) >> 3) & 0x70))

// ---- baseline-PTX tensor ops ----
__device__ __forceinline__ void ldsm4(uint32_t (&r)[4], uint32_t addr) {
    asm volatile("ldmatrix.sync.aligned.m8n8.x4.shared.b16 {%0,%1,%2,%3}, [%4];"
                 : "=r"(r[0]), "=r"(r[1]), "=r"(r[2]), "=r"(r[3]) : "r"(addr));
}
__device__ __forceinline__ void mma16816(float (&d)[4], const uint32_t (&a)[4],
                                         uint32_t b0, uint32_t b1) {
    asm volatile("mma.sync.aligned.m16n8k16.row.col.f32.f16.f16.f32 "
                 "{%0,%1,%2,%3}, {%4,%5,%6,%7}, {%8,%9}, {%0,%1,%2,%3};"
                 : "+f"(d[0]), "+f"(d[1]), "+f"(d[2]), "+f"(d[3])
                 : "r"(a[0]), "r"(a[1]), "r"(a[2]), "r"(a[3]), "r"(b0), "r"(b1));
}
__device__ __forceinline__ void cpasync16(uint32_t saddr, const void* g) {
    asm volatile("cp.async.cg.shared.global [%0], [%1], 16;" :: "r"(saddr), "l"(g));
}
#define CP_COMMIT() asm volatile("cp.async.commit_group;" ::: "memory")
#define CP_WAIT(N)  asm volatile("cp.async.wait_group %0;" :: "n"(N) : "memory")

// ================= setup =================
__device__ __forceinline__ void fold_single(int t0, int stride,
        const float* __restrict__ W, const float* __restrict__ g, const float* __restrict__ v,
        __half* wd, int C, int Kdst, int Ksrc, int Koff) {
    for (int idx = t0; idx < C * Kdst; idx += stride) {
        int c = idx / Kdst, k = idx - c * Kdst;
        float s = g[c] * rsqrtf(v[c] + EPSF);
        wd[idx] = __float2half_rn(s * W[(size_t)c * Ksrc + Koff + k]);
    }
}
__device__ __forceinline__ void fold_bias(int t0, int stride,
        const float* b, const float* g, const float* be, const float* m, const float* v,
        float* bf, int C) {
    for (int i = t0; i < C; i += stride) {
        float s = g[i] * rsqrtf(v[i] + EPSF);
        bf[i] = s * b[i] + be[i] - s * m[i];
    }
}

__global__ void setup_kernel(const int* __restrict__ npts,
    const float* W1, const float* b1, const float* g1, const float* be1, const float* m1, const float* v1,
    const float* W2, const float* b2, const float* g2, const float* be2, const float* m2, const float* v2,
    const float* W3, const float* b3, const float* g3, const float* be3, const float* m3, const float* v3,
    const float* W4, const float* b4, const float* g4, const float* be4, const float* m4, const float* v4) {
    const int stride = gridDim.x * blockDim.x;
    const int t0 = blockIdx.x * blockDim.x + threadIdx.x;

    for (int c = t0; c < 128; c += stride) {
        float s = g1[c] * rsqrtf(v1[c] + EPSF);
        d_W1c[c * 4 + 0] = s * W1[c * 3 + 0];
        d_W1c[c * 4 + 1] = s * W1[c * 3 + 1];
        d_W1c[c * 4 + 2] = s * W1[c * 3 + 2];
        d_W1c[c * 4 + 3] = s * b1[c] + be1[c] - s * m1[c];
    }
    fold_single(t0, stride, W2, g2, v2, d_w2, 256,  128, 128, 0);
    fold_single(t0, stride, W3, g3, v3, d_w3, 512,  256, 512, 256);
    fold_single(t0, stride, W4, g4, v4, d_w4, 1024, 512, 512, 0);
    fold_bias(t0, stride, b2, g2, be2, m2, v2, d_b2f, 256);
    fold_bias(t0, stride, b3, g3, be3, m3, v3, d_b3f, 512);
    fold_bias(t0, stride, b4, g4, be4, m4, v4, d_b4f, 1024);

    int cum[BSEG];
    {
        int a = 0;
        #pragma unroll
        for (int t = 0; t < BSEG; t++) { a += __ldg(&npts[t]); cum[t] = a; }
    }
    for (int j = t0; j < NPTS; j += stride) {
        int s = 0;
        #pragma unroll
        for (int t = 0; t < BSEG - 1; t++) s += (j >= cum[t]);
        d_seg[j] = s;
    }
    for (int i = t0; i < BSEG * 1024; i += stride) d_vkey[i] = 0u;
    for (int i = t0; i < BSEG * 256;  i += stride) d_gkey[i] = 0u;
}

__global__ void fin_v_kernel(float* __restrict__ out) {
    int i = blockIdx.x * blockDim.x + threadIdx.x;
    if (i < BSEG * 1024) out[i] = key2f(d_vkey[i]);
}
__global__ void k_u_kernel(const float* __restrict__ W3,
                           const float* __restrict__ g3,
                           const float* __restrict__ v3) {
    int w = (blockIdx.x * blockDim.x + threadIdx.x) >> 5;
    int lane = threadIdx.x & 31;
    if (w >= 512 * BSEG) return;
    int m = w >> 4, s = w & 15;
    float acc = 0.0f;
    for (int r = lane; r < 256; r += 32)
        acc += W3[(size_t)m * 512 + r] * key2f(d_gkey[s * 256 + r]);
    #pragma unroll
    for (int o = 16; o; o >>= 1) acc += __shfl_xor_sync(0xffffffffu, acc, o);
    if (lane == 0) d_u[m * BSEG + s] = g3[m] * rsqrtf(v3[m] + EPSF) * acc;
}

// ================= mma.sync GEMM (8 warps/CTA 32x64 tiles, 2 CTAs/SM) =================
// CTA: 128 pts x 128 chans; 8 warps 4(m) x 2(n); per-warp 32x64.
// K chunks of 64; 3 stages; swizzled 128B rows. 98 KB smem/CTA -> 2 CTAs/SM.
// CFG0 fuses layer-1.
#define ROWB    128
#define ATILE   (128 * ROWB)          // 16384
#define BTILE   (128 * ROWB)          // 16384
#define STAGEB  (ATILE + BTILE)       // 32768
#define NSTAGE  3
#define RED_OFF (NSTAGE * STAGEB)     // float red[8][64] = 2048 B
#define MM_SMEM (RED_OFF + 2048)      // 100352 B

template<int CFG>
__global__ void __launch_bounds__(256, 2) mm_kernel(const float* __restrict__ xg) {
    constexpr int K    = (CFG == 0) ? 128 : (CFG == 1) ? 256 : 512;
    constexpr int MOUT = (CFG == 0) ? 256 : (CFG == 1) ? 512 : 1024;
    constexpr int KC   = K / 64;
    constexpr bool SEGMAX = (CFG != 1);
    constexpr bool STORE  = (CFG != 2);
    constexpr bool FUSE1  = (CFG == 0);

    const __half* __restrict__ Ain = (CFG == 1) ? d_a2 : d_a3;   // unused for CFG0
    const __half* __restrict__ Bw  = (CFG == 0) ? d_w2 : (CFG == 1) ? d_w3 : d_w4;
    const float* __restrict__ bias = (CFG == 0) ? d_b2f : (CFG == 1) ? d_b3f : d_b4f;
    __half* Oa = (CFG == 0) ? d_a2 : d_a3;
    unsigned* key = (CFG == 0) ? d_gkey : d_vkey;

    extern __shared__ char smem[];
    const uint32_t sb = smem_to_u32(smem);
    const int tid = threadIdx.x, wid = tid >> 5, lane = tid & 31;
    const int wm = wid & 3, wn = wid >> 2;
    const int n0 = blockIdx.x * 128;
    const int pt0 = blockIdx.y * 128;

    float acc[2][8][4];
    #pragma unroll
    for (int mi = 0; mi < 2; mi++)
        #pragma unroll
        for (int nt = 0; nt < 8; nt++)
            #pragma unroll
            for (int q = 0; q < 4; q++) acc[mi][nt][q] = 0.0f;

    auto load_B = [&](int kc, int buf) {
        const int k0 = kc * 64;
        const uint32_t base = sb + (uint32_t)buf * STAGEB;
        #pragma unroll
        for (int i = 0; i < 4; i++) {
            int idx = i * 256 + tid;              // 0..1023
            int row = idx >> 3, c8 = idx & 7;
            cpasync16(base + ATILE + SW128((uint32_t)(row * ROWB + c8 * 16)),
                      Bw + (size_t)(n0 + row) * K + k0 + c8 * 8);
        }
    };
    auto load_chunk = [&](int kc, int buf) {
        const int k0 = kc * 64;
        const uint32_t base = sb + (uint32_t)buf * STAGEB;
        #pragma unroll
        for (int i = 0; i < 4; i++) {
            int idx = i * 256 + tid;
            int row = idx >> 3, c8 = idx & 7;
            cpasync16(base + SW128((uint32_t)(row * ROWB + c8 * 16)),
                      Ain + (size_t)(pt0 + row) * K + k0 + c8 * 8);
        }
        load_B(kc, buf);
        CP_COMMIT();
    };

    auto compute = [&](int buf) {
        const uint32_t ab = sb + (uint32_t)buf * STAGEB;
        const uint32_t bbB = ab + ATILE;
        #pragma unroll
        for (int kk = 0; kk < 4; kk++) {
            const uint32_t col = (uint32_t)((lane >> 4) * 16 + kk * 32);  // bytes
            uint32_t a_f[2][4];
            #pragma unroll
            for (int mi = 0; mi < 2; mi++) {
                uint32_t row = (uint32_t)(wm * 32 + mi * 16 + (lane & 15));
                ldsm4(a_f[mi], ab + SW128(row * ROWB + col));
            }
            #pragma unroll
            for (int nt4 = 0; nt4 < 4; nt4++) {
                uint32_t row = (uint32_t)(wn * 64 + nt4 * 16 + (lane & 15));
                uint32_t b_f[4];
                ldsm4(b_f, bbB + SW128(row * ROWB + col));
                #pragma unroll
                for (int mi = 0; mi < 2; mi++) {
                    mma16816(acc[mi][nt4 * 2 + 0], a_f[mi], b_f[0], b_f[2]);
                    mma16816(acc[mi][nt4 * 2 + 1], a_f[mi], b_f[1], b_f[3]);
                }
            }
        }
    };

    if (FUSE1) {
        load_B(0, 0); CP_COMMIT();
        load_B(1, 1); CP_COMMIT();
        // layer-1: 2 threads per point; each handles 64 channels -> one K-chunk's A row half
        {
            const int pt = pt0 + (tid >> 1);
            const int half = tid & 1;
            const int row = tid >> 1;
            const float x0 = xg[pt], x1 = xg[NPTS + pt], x2 = xg[2 * NPTS + pt];
            #pragma unroll
            for (int g = 0; g < 8; g++) {
                __half2 h2[4];
                #pragma unroll
                for (int q = 0; q < 4; q++) {
                    #pragma unroll
                    for (int r = 0; r < 2; r++) {
                        const int c = (half * 8 + g) * 8 + q * 2 + r;
                        const float* w = &d_W1c[c * 4];
                        float v = fmaxf(__ldg(&w[3]) + __ldg(&w[0]) * x0
                                      + __ldg(&w[1]) * x1 + __ldg(&w[2]) * x2, 0.0f);
                        if (r == 0) h2[q].x = __float2half_rn(v);
                        else        h2[q].y = __float2half_rn(v);
                    }
                }
                uint32_t off = (uint32_t)half * STAGEB
                             + SW128((uint32_t)(row * ROWB + g * 16));
                *reinterpret_cast<uint4*>(smem + off) = *reinterpret_cast<uint4*>(h2);
            }
        }
    } else {
        load_chunk(0, 0);
        if (KC > 1) load_chunk(1, 1);
    }

    #pragma unroll 1
    for (int kc = 0; kc < KC; kc++) {
        if (kc + 1 < KC) { CP_WAIT(1); } else { CP_WAIT(0); }
        __syncthreads();
        if (!FUSE1 && kc + 2 < KC) load_chunk(kc + 2, (kc + 2) % NSTAGE);
        compute(FUSE1 ? kc : (kc % NSTAGE));
    }

    // ---- epilogue ----
    int ptr_[4], sg[4];
    #pragma unroll
    for (int mi = 0; mi < 2; mi++)
        #pragma unroll
        for (int h = 0; h < 2; h++) {
            int p = pt0 + wm * 32 + mi * 16 + (lane >> 2) + h * 8;
            ptr_[mi * 2 + h] = p;
            sg[mi * 2 + h] = d_seg[p];
        }
    const int cbase = n0 + wn * 64 + (lane & 3) * 2;

    #pragma unroll
    for (int mi = 0; mi < 2; mi++) {
        #pragma unroll
        for (int h = 0; h < 2; h++) {
            const int p = ptr_[mi * 2 + h];
            const int seg = sg[mi * 2 + h];
            #pragma unroll
            for (int nt = 0; nt < 8; nt++) {
                const int c = cbase + nt * 8;
                float v0 = acc[mi][nt][h * 2 + 0] + __ldg(&bias[c]);
                float v1 = acc[mi][nt][h * 2 + 1] + __ldg(&bias[c + 1]);
                if (CFG == 1) {
                    v0 = fmaxf(v0 + d_u[c * BSEG + seg], 0.0f);
                    v1 = fmaxf(v1 + d_u[(c + 1) * BSEG + seg], 0.0f);
                }
                acc[mi][nt][h * 2 + 0] = v0;
                acc[mi][nt][h * 2 + 1] = v1;
                if (STORE) {
                    __half2 hh;
                    hh.x = __float2half_rn(v0);
                    hh.y = __float2half_rn(v1);
                    *reinterpret_cast<uint32_t*>(&Oa[(size_t)p * MOUT + c]) =
                        *reinterpret_cast<uint32_t*>(&hh);
                }
            }
        }
    }

    if (SEGMAX) {
        float* red = reinterpret_cast<float*>(smem + RED_OFF);
        const int s_lo = d_seg[pt0], s_hi = d_seg[pt0 + 127];
        const int np = (s_lo == s_hi) ? 1 : 2;
        for (int pass = 0; pass < np; pass++) {
            const int s = pass ? s_hi : s_lo;
            float cm[8][2];
            #pragma unroll
            for (int nt = 0; nt < 8; nt++) { cm[nt][0] = -3.402823466e38f; cm[nt][1] = -3.402823466e38f; }
            #pragma unroll
            for (int mi = 0; mi < 2; mi++)
                #pragma unroll
                for (int h = 0; h < 2; h++)
                    if (sg[mi * 2 + h] == s) {
                        #pragma unroll
                        for (int nt = 0; nt < 8; nt++) {
                            cm[nt][0] = fmaxf(cm[nt][0], acc[mi][nt][h * 2 + 0]);
                            cm[nt][1] = fmaxf(cm[nt][1], acc[mi][nt][h * 2 + 1]);
                        }
                    }
            #pragma unroll
            for (int o = 4; o < 32; o <<= 1)
                #pragma unroll
                for (int nt = 0; nt < 8; nt++) {
                    cm[nt][0] = fmaxf(cm[nt][0], __shfl_xor_sync(0xffffffffu, cm[nt][0], o));
                    cm[nt][1] = fmaxf(cm[nt][1], __shfl_xor_sync(0xffffffffu, cm[nt][1], o));
                }
            __syncthreads();
            if ((lane >> 2) == 0) {
                #pragma unroll
                for (int nt = 0; nt < 8; nt++) {
                    red[wid * 64 + nt * 8 + (lane & 3) * 2 + 0] = cm[nt][0];
                    red[wid * 64 + nt * 8 + (lane & 3) * 2 + 1] = cm[nt][1];
                }
            }
            __syncthreads();
            if ((wid & 3) == 0) {   // wid 0 (wn=0), wid 4 (wn=1)
                const int wgrp = wid >> 2;
                #pragma unroll
                for (int cc = 0; cc < 2; cc++) {
                    const int col = lane * 2 + cc;
                    float m = red[(wgrp * 4 + 0) * 64 + col];
                    #pragma unroll
                    for (int w = 1; w < 4; w++)
                        m = fmaxf(m, red[(wgrp * 4 + w) * 64 + col]);
                    atomicMax(&key[s * MOUT + n0 + wgrp * 64 + col], f2key(m));
                }
            }
        }
    }
}

// ================= launch =================
extern "C" void kernel_launch(void* const* d_in, const int* in_sizes, int n_in,
                              void* d_out, int out_size) {
    const float* x    = (const float*)d_in[0];
    const int*   npts = (const int*  )d_in[1];
    const float *W1 = (const float*)d_in[2],  *b1 = (const float*)d_in[3],
                *g1 = (const float*)d_in[4],  *be1= (const float*)d_in[5],
                *m1 = (const float*)d_in[6],  *v1 = (const float*)d_in[7];
    const float *W2 = (const float*)d_in[8],  *b2 = (const float*)d_in[9],
                *g2 = (const float*)d_in[10], *be2= (const float*)d_in[11],
                *m2 = (const float*)d_in[12], *v2 = (const float*)d_in[13];
    const float *W3 = (const float*)d_in[14], *b3 = (const float*)d_in[15],
                *g3 = (const float*)d_in[16], *be3= (const float*)d_in[17],
                *m3 = (const float*)d_in[18], *v3 = (const float*)d_in[19];
    const float *W4 = (const float*)d_in[20], *b4 = (const float*)d_in[21],
                *g4 = (const float*)d_in[22], *be4= (const float*)d_in[23],
                *m4 = (const float*)d_in[24], *v4 = (const float*)d_in[25];

    cudaFuncSetAttribute(mm_kernel<0>, cudaFuncAttributeMaxDynamicSharedMemorySize, MM_SMEM);
    cudaFuncSetAttribute(mm_kernel<1>, cudaFuncAttributeMaxDynamicSharedMemorySize, MM_SMEM);
    cudaFuncSetAttribute(mm_kernel<2>, cudaFuncAttributeMaxDynamicSharedMemorySize, MM_SMEM);

    setup_kernel<<<512, 256>>>(npts,
        W1, b1, g1, be1, m1, v1,  W2, b2, g2, be2, m2, v2,
        W3, b3, g3, be3, m3, v3,  W4, b4, g4, be4, m4, v4);

    mm_kernel<0><<<dim3(2, NPTS / 128), 256, MM_SMEM>>>(x);  // #2: f (+g segmax), layer1 fused
    k_u_kernel<<<1024, 256>>>(W3, g3, v3);                   // #3
    mm_kernel<1><<<dim3(4, NPTS / 128), 256, MM_SMEM>>>(x);  // #4: h3  <- ncu captures this
    mm_kernel<2><<<dim3(8, NPTS / 128), 256, MM_SMEM>>>(x);  // #5: v segmax
    fin_v_kernel<<<64, 256>>>((float*)d_out);                // #6
}

// round 17
// speedup vs baseline: 1.4877x; 1.4788x over previous
#include <cuda_runtime.h>
#include <cuda_fp16.h>
#include <cstdint>

#define NPTS 131072
#define BSEG 16
#define EPSF 1e-5f

// ================= device scratch (allocation-free) =================
__device__ __half d_a2[(size_t)NPTS * 256];
__device__ __half d_a3[(size_t)NPTS * 512];
__device__ __half d_w2[256 * 128];
__device__ __half d_w3[512 * 256];
__device__ __half d_w4[1024 * 512];
__device__ float d_W1c[128 * 4];            // [c][w0,w1,w2,bias]
__device__ float d_b2f[256], d_b3f[512], d_b4f[1024];
__device__ float d_u[512 * BSEG];           // per-segment bias for layer3
__device__ unsigned d_gkey[BSEG * 256];
__device__ unsigned d_vkey[BSEG * 1024];
__device__ int d_seg[NPTS];

// ================= helpers =================
__device__ __forceinline__ unsigned f2key(float f) {
    unsigned u = __float_as_uint(f);
    return (u & 0x80000000u) ? ~u : (u | 0x80000000u);
}
__device__ __forceinline__ float key2f(unsigned k) {
    return (k & 0x80000000u) ? __uint_as_float(k & 0x7FFFFFFFu)
                             : __uint_as_float(~k);
}
__device__ __forceinline__ uint32_t smem_to_u32(const void* p) {
    uint32_t a;
    asm("{ .reg .u64 t; cvta.to.shared.u64 t, %1; cvt.u32.u64 %0, t; }" : "=r"(a) : "l"(p));
    return a;
}
#define SW128(o) ((o) ^ (((o) >> 3) & 0x70))

// ---- baseline-PTX tensor ops ----
__device__ __forceinline__ void ldsm4(uint32_t (&r)[4], uint32_t addr) {
    asm volatile("ldmatrix.sync.aligned.m8n8.x4.shared.b16 {%0,%1,%2,%3}, [%4];"
                 : "=r"(r[0]), "=r"(r[1]), "=r"(r[2]), "=r"(r[3]) : "r"(addr));
}
__device__ __forceinline__ void mma16816(float (&d)[4], const uint32_t (&a)[4],
                                         uint32_t b0, uint32_t b1) {
    asm volatile("mma.sync.aligned.m16n8k16.row.col.f32.f16.f16.f32 "
                 "{%0,%1,%2,%3}, {%4,%5,%6,%7}, {%8,%9}, {%0,%1,%2,%3};"
                 : "+f"(d[0]), "+f"(d[1]), "+f"(d[2]), "+f"(d[3])
                 : "r"(a[0]), "r"(a[1]), "r"(a[2]), "r"(a[3]), "r"(b0), "r"(b1));
}
__device__ __forceinline__ void cpasync16(uint32_t saddr, const void* g) {
    asm volatile("cp.async.cg.shared.global [%0], [%1], 16;" :: "r"(saddr), "l"(g));
}
#define CP_COMMIT() asm volatile("cp.async.commit_group;" ::: "memory")
#define CP_WAIT(N)  asm volatile("cp.async.wait_group %0;" :: "n"(N) : "memory")

// ================= setup =================
__device__ __forceinline__ void fold_single(int t0, int stride,
        const float* __restrict__ W, const float* __restrict__ g, const float* __restrict__ v,
        __half* wd, int C, int Kdst, int Ksrc, int Koff) {
    for (int idx = t0; idx < C * Kdst; idx += stride) {
        int c = idx / Kdst, k = idx - c * Kdst;
        float s = g[c] * rsqrtf(v[c] + EPSF);
        wd[idx] = __float2half_rn(s * W[(size_t)c * Ksrc + Koff + k]);
    }
}
__device__ __forceinline__ void fold_bias(int t0, int stride,
        const float* b, const float* g, const float* be, const float* m, const float* v,
        float* bf, int C) {
    for (int i = t0; i < C; i += stride) {
        float s = g[i] * rsqrtf(v[i] + EPSF);
        bf[i] = s * b[i] + be[i] - s * m[i];
    }
}

__global__ void setup_kernel(const int* __restrict__ npts,
    const float* W1, const float* b1, const float* g1, const float* be1, const float* m1, const float* v1,
    const float* W2, const float* b2, const float* g2, const float* be2, const float* m2, const float* v2,
    const float* W3, const float* b3, const float* g3, const float* be3, const float* m3, const float* v3,
    const float* W4, const float* b4, const float* g4, const float* be4, const float* m4, const float* v4) {
    const int stride = gridDim.x * blockDim.x;
    const int t0 = blockIdx.x * blockDim.x + threadIdx.x;

    for (int c = t0; c < 128; c += stride) {
        float s = g1[c] * rsqrtf(v1[c] + EPSF);
        d_W1c[c * 4 + 0] = s * W1[c * 3 + 0];
        d_W1c[c * 4 + 1] = s * W1[c * 3 + 1];
        d_W1c[c * 4 + 2] = s * W1[c * 3 + 2];
        d_W1c[c * 4 + 3] = s * b1[c] + be1[c] - s * m1[c];
    }
    fold_single(t0, stride, W2, g2, v2, d_w2, 256,  128, 128, 0);
    fold_single(t0, stride, W3, g3, v3, d_w3, 512,  256, 512, 256);
    fold_single(t0, stride, W4, g4, v4, d_w4, 1024, 512, 512, 0);
    fold_bias(t0, stride, b2, g2, be2, m2, v2, d_b2f, 256);
    fold_bias(t0, stride, b3, g3, be3, m3, v3, d_b3f, 512);
    fold_bias(t0, stride, b4, g4, be4, m4, v4, d_b4f, 1024);

    int cum[BSEG];
    {
        int a = 0;
        #pragma unroll
        for (int t = 0; t < BSEG; t++) { a += __ldg(&npts[t]); cum[t] = a; }
    }
    for (int j = t0; j < NPTS; j += stride) {
        int s = 0;
        #pragma unroll
        for (int t = 0; t < BSEG - 1; t++) s += (j >= cum[t]);
        d_seg[j] = s;
    }
    for (int i = t0; i < BSEG * 1024; i += stride) d_vkey[i] = 0u;
    for (int i = t0; i < BSEG * 256;  i += stride) d_gkey[i] = 0u;
}

__global__ void fin_v_kernel(float* __restrict__ out) {
    int i = blockIdx.x * blockDim.x + threadIdx.x;
    if (i < BSEG * 1024) out[i] = key2f(d_vkey[i]);
}
__global__ void k_u_kernel(const float* __restrict__ W3,
                           const float* __restrict__ g3,
                           const float* __restrict__ v3) {
    int w = (blockIdx.x * blockDim.x + threadIdx.x) >> 5;
    int lane = threadIdx.x & 31;
    if (w >= 512 * BSEG) return;
    int m = w >> 4, s = w & 15;
    float acc = 0.0f;
    for (int r = lane; r < 256; r += 32)
        acc += W3[(size_t)m * 512 + r] * key2f(d_gkey[s * 256 + r]);
    #pragma unroll
    for (int o = 16; o; o >>= 1) acc += __shfl_xor_sync(0xffffffffu, acc, o);
    if (lane == 0) d_u[m * BSEG + s] = g3[m] * rsqrtf(v3[m] + EPSF) * acc;
}

// ================= mma.sync GEMM (4 warps/CTA 32x64 tiles, 4 CTAs/SM) =================
// CTA: 128 pts x 64 chans; 4 warps wm=wid (32 pts each), wn=0 (all 64 chans).
// K chunks of 64; 2 stages; swizzled 128B rows. ~50 KB smem/CTA -> 4 CTAs/SM,
// 16 warps/SM in 4 independent barrier domains.
#define ROWB    128
#define ATILE   (128 * ROWB)          // 16384 (A: 128 rows)
#define BTILE   (64 * ROWB)           // 8192  (B: 64 rows)
#define STAGEB  (ATILE + BTILE)       // 24576
#define NSTAGE  2
#define RED_OFF (NSTAGE * STAGEB)     // float red[4][64] = 1024 B
#define MM_SMEM (RED_OFF + 1024)      // 50176 B

template<int CFG>
__global__ void __launch_bounds__(128, 4) mm_kernel(const float* __restrict__ xg) {
    constexpr int K    = (CFG == 0) ? 128 : (CFG == 1) ? 256 : 512;
    constexpr int MOUT = (CFG == 0) ? 256 : (CFG == 1) ? 512 : 1024;
    constexpr int KC   = K / 64;
    constexpr bool SEGMAX = (CFG != 1);
    constexpr bool STORE  = (CFG != 2);
    constexpr bool FUSE1  = (CFG == 0);

    const __half* __restrict__ Ain = (CFG == 1) ? d_a2 : d_a3;   // unused for CFG0
    const __half* __restrict__ Bw  = (CFG == 0) ? d_w2 : (CFG == 1) ? d_w3 : d_w4;
    const float* __restrict__ bias = (CFG == 0) ? d_b2f : (CFG == 1) ? d_b3f : d_b4f;
    __half* Oa = (CFG == 0) ? d_a2 : d_a3;
    unsigned* key = (CFG == 0) ? d_gkey : d_vkey;

    extern __shared__ char smem[];
    const uint32_t sb = smem_to_u32(smem);
    const int tid = threadIdx.x, wid = tid >> 5, lane = tid & 31;
    const int wm = wid;                    // 4 warps stacked along points
    const int n0 = blockIdx.x * 64;
    const int pt0 = blockIdx.y * 128;

    float acc[2][8][4];
    #pragma unroll
    for (int mi = 0; mi < 2; mi++)
        #pragma unroll
        for (int nt = 0; nt < 8; nt++)
            #pragma unroll
            for (int q = 0; q < 4; q++) acc[mi][nt][q] = 0.0f;

    auto load_B = [&](int kc, int buf) {
        const int k0 = kc * 64;
        const uint32_t base = sb + (uint32_t)buf * STAGEB;
        #pragma unroll
        for (int i = 0; i < 4; i++) {              // 64 rows x 8 16B-chunks = 512
            int idx = i * 128 + tid;
            int row = idx >> 3, c8 = idx & 7;
            cpasync16(base + ATILE + SW128((uint32_t)(row * ROWB + c8 * 16)),
                      Bw + (size_t)(n0 + row) * K + k0 + c8 * 8);
        }
    };
    auto load_chunk = [&](int kc, int buf) {
        const int k0 = kc * 64;
        const uint32_t base = sb + (uint32_t)buf * STAGEB;
        #pragma unroll
        for (int i = 0; i < 8; i++) {              // 128 rows x 8 = 1024
            int idx = i * 128 + tid;
            int row = idx >> 3, c8 = idx & 7;
            cpasync16(base + SW128((uint32_t)(row * ROWB + c8 * 16)),
                      Ain + (size_t)(pt0 + row) * K + k0 + c8 * 8);
        }
        load_B(kc, buf);
        CP_COMMIT();
    };

    auto compute = [&](int buf) {
        const uint32_t ab = sb + (uint32_t)buf * STAGEB;
        const uint32_t bbB = ab + ATILE;
        #pragma unroll
        for (int kk = 0; kk < 4; kk++) {
            const uint32_t col = (uint32_t)((lane >> 4) * 16 + kk * 32);  // bytes
            uint32_t a_f[2][4];
            #pragma unroll
            for (int mi = 0; mi < 2; mi++) {
                uint32_t row = (uint32_t)(wm * 32 + mi * 16 + (lane & 15));
                ldsm4(a_f[mi], ab + SW128(row * ROWB + col));
            }
            #pragma unroll
            for (int nt4 = 0; nt4 < 4; nt4++) {
                uint32_t row = (uint32_t)(nt4 * 16 + (lane & 15));
                uint32_t b_f[4];
                ldsm4(b_f, bbB + SW128(row * ROWB + col));
                #pragma unroll
                for (int mi = 0; mi < 2; mi++) {
                    mma16816(acc[mi][nt4 * 2 + 0], a_f[mi], b_f[0], b_f[2]);
                    mma16816(acc[mi][nt4 * 2 + 1], a_f[mi], b_f[1], b_f[3]);
                }
            }
        }
    };

    if (FUSE1) {
        load_B(0, 0); CP_COMMIT();
        load_B(1, 1); CP_COMMIT();
        // layer-1: 1 thread per point, all 128 channels -> both chunks' A rows
        {
            const int pt = pt0 + tid;
            const float x0 = xg[pt], x1 = xg[NPTS + pt], x2 = xg[2 * NPTS + pt];
            #pragma unroll
            for (int g = 0; g < 16; g++) {         // 16 groups of 8 channels
                __half2 h2[4];
                #pragma unroll
                for (int q = 0; q < 4; q++) {
                    #pragma unroll
                    for (int r = 0; r < 2; r++) {
                        const int c = g * 8 + q * 2 + r;
                        const float* w = &d_W1c[c * 4];
                        float v = fmaxf(__ldg(&w[3]) + __ldg(&w[0]) * x0
                                      + __ldg(&w[1]) * x1 + __ldg(&w[2]) * x2, 0.0f);
                        if (r == 0) h2[q].x = __float2half_rn(v);
                        else        h2[q].y = __float2half_rn(v);
                    }
                }
                const int chunk = g >> 3;          // channels 0-63 -> buf0, 64-127 -> buf1
                const int c8 = g & 7;
                uint32_t off = (uint32_t)chunk * STAGEB
                             + SW128((uint32_t)(tid * ROWB + c8 * 16));
                *reinterpret_cast<uint4*>(smem + off) = *reinterpret_cast<uint4*>(h2);
            }
        }
        #pragma unroll 1
        for (int kc = 0; kc < KC; kc++) {
            if (kc + 1 < KC) { CP_WAIT(1); } else { CP_WAIT(0); }
            __syncthreads();
            compute(kc & 1);
        }
    } else {
        load_chunk(0, 0);
        #pragma unroll 1
        for (int kc = 0; kc < KC; kc++) {
            CP_WAIT(0);
            __syncthreads();
            if (kc + 1 < KC) load_chunk(kc + 1, (kc + 1) & 1);
            compute(kc & 1);
        }
    }

    // ---- epilogue ----
    int ptr_[4], sg[4];
    #pragma unroll
    for (int mi = 0; mi < 2; mi++)
        #pragma unroll
        for (int h = 0; h < 2; h++) {
            int p = pt0 + wm * 32 + mi * 16 + (lane >> 2) + h * 8;
            ptr_[mi * 2 + h] = p;
            sg[mi * 2 + h] = d_seg[p];
        }
    const int cbase = n0 + (lane & 3) * 2;

    #pragma unroll
    for (int mi = 0; mi < 2; mi++) {
        #pragma unroll
        for (int h = 0; h < 2; h++) {
            const int p = ptr_[mi * 2 + h];
            const int seg = sg[mi * 2 + h];
            #pragma unroll
            for (int nt = 0; nt < 8; nt++) {
                const int c = cbase + nt * 8;
                float v0 = acc[mi][nt][h * 2 + 0] + __ldg(&bias[c]);
                float v1 = acc[mi][nt][h * 2 + 1] + __ldg(&bias[c + 1]);
                if (CFG == 1) {
                    v0 = fmaxf(v0 + d_u[c * BSEG + seg], 0.0f);
                    v1 = fmaxf(v1 + d_u[(c + 1) * BSEG + seg], 0.0f);
                }
                acc[mi][nt][h * 2 + 0] = v0;
                acc[mi][nt][h * 2 + 1] = v1;
                if (STORE) {
                    __half2 hh;
                    hh.x = __float2half_rn(v0);
                    hh.y = __float2half_rn(v1);
                    *reinterpret_cast<uint32_t*>(&Oa[(size_t)p * MOUT + c]) =
                        *reinterpret_cast<uint32_t*>(&hh);
                }
            }
        }
    }

    if (SEGMAX) {
        float* red = reinterpret_cast<float*>(smem + RED_OFF);
        const int s_lo = d_seg[pt0], s_hi = d_seg[pt0 + 127];
        const int np = (s_lo == s_hi) ? 1 : 2;
        for (int pass = 0; pass < np; pass++) {
            const int s = pass ? s_hi : s_lo;
            float cm[8][2];
            #pragma unroll
            for (int nt = 0; nt < 8; nt++) { cm[nt][0] = -3.402823466e38f; cm[nt][1] = -3.402823466e38f; }
            #pragma unroll
            for (int mi = 0; mi < 2; mi++)
                #pragma unroll
                for (int h = 0; h < 2; h++)
                    if (sg[mi * 2 + h] == s) {
                        #pragma unroll
                        for (int nt = 0; nt < 8; nt++) {
                            cm[nt][0] = fmaxf(cm[nt][0], acc[mi][nt][h * 2 + 0]);
                            cm[nt][1] = fmaxf(cm[nt][1], acc[mi][nt][h * 2 + 1]);
                        }
                    }
            #pragma unroll
            for (int o = 4; o < 32; o <<= 1)
                #pragma unroll
                for (int nt = 0; nt < 8; nt++) {
                    cm[nt][0] = fmaxf(cm[nt][0], __shfl_xor_sync(0xffffffffu, cm[nt][0], o));
                    cm[nt][1] = fmaxf(cm[nt][1], __shfl_xor_sync(0xffffffffu, cm[nt][1], o));
                }
            __syncthreads();
            if ((lane >> 2) == 0) {
                #pragma unroll
                for (int nt = 0; nt < 8; nt++) {
                    red[wid * 64 + nt * 8 + (lane & 3) * 2 + 0] = cm[nt][0];
                    red[wid * 64 + nt * 8 + (lane & 3) * 2 + 1] = cm[nt][1];
                }
            }
            __syncthreads();
            if (wid == 0) {
                #pragma unroll
                for (int cc = 0; cc < 2; cc++) {
                    const int col = lane * 2 + cc;
                    float m = red[col];
                    #pragma unroll
                    for (int w = 1; w < 4; w++)
                        m = fmaxf(m, red[w * 64 + col]);
                    atomicMax(&key[s * MOUT + n0 + col], f2key(m));
                }
            }
        }
    }
}

// ================= launch =================
extern "C" void kernel_launch(void* const* d_in, const int* in_sizes, int n_in,
                              void* d_out, int out_size) {
    const float* x    = (const float*)d_in[0];
    const int*   npts = (const int*  )d_in[1];
    const float *W1 = (const float*)d_in[2],  *b1 = (const float*)d_in[3],
                *g1 = (const float*)d_in[4],  *be1= (const float*)d_in[5],
                *m1 = (const float*)d_in[6],  *v1 = (const float*)d_in[7];
    const float *W2 = (const float*)d_in[8],  *b2 = (const float*)d_in[9],
                *g2 = (const float*)d_in[10], *be2= (const float*)d_in[11],
                *m2 = (const float*)d_in[12], *v2 = (const float*)d_in[13];
    const float *W3 = (const float*)d_in[14], *b3 = (const float*)d_in[15],
                *g3 = (const float*)d_in[16], *be3= (const float*)d_in[17],
                *m3 = (const float*)d_in[18], *v3 = (const float*)d_in[19];
    const float *W4 = (const float*)d_in[20], *b4 = (const float*)d_in[21],
                *g4 = (const float*)d_in[22], *be4= (const float*)d_in[23],
                *m4 = (const float*)d_in[24], *v4 = (const float*)d_in[25];

    cudaFuncSetAttribute(mm_kernel<0>, cudaFuncAttributeMaxDynamicSharedMemorySize, MM_SMEM);
    cudaFuncSetAttribute(mm_kernel<1>, cudaFuncAttributeMaxDynamicSharedMemorySize, MM_SMEM);
    cudaFuncSetAttribute(mm_kernel<2>, cudaFuncAttributeMaxDynamicSharedMemorySize, MM_SMEM);

    setup_kernel<<<512, 256>>>(npts,
        W1, b1, g1, be1, m1, v1,  W2, b2, g2, be2, m2, v2,
        W3, b3, g3, be3, m3, v3,  W4, b4, g4, be4, m4, v4);

    mm_kernel<0><<<dim3(4,  NPTS / 128), 128, MM_SMEM>>>(x); // #2: f (+g segmax), layer1 fused
    k_u_kernel<<<1024, 256>>>(W3, g3, v3);                   // #3
    mm_kernel<1><<<dim3(8,  NPTS / 128), 128, MM_SMEM>>>(x); // #4: h3  <- ncu captures this
    mm_kernel<2><<<dim3(16, NPTS / 128), 128, MM_SMEM>>>(x); // #5: v segmax
    fin_v_kernel<<<64, 256>>>((float*)d_out);                // #6
}